// round 3
// baseline (speedup 1.0000x reference)
#include <cuda_runtime.h>

// Problem constants
#define Nn 8
#define Cc 16
#define Ll 1024
#define Dd 7
#define Hh 16
#define SZ 112      // C*D = H*dh
#define PAD 8       // padded head_dim for float4 access

// Scratch: Q/K/V in [N, H, L, PAD] layout. Q pre-scaled by log2(e)/32.
__device__ float g_Q[Nn * Hh * Ll * PAD];
__device__ float g_K[Nn * Hh * Ll * PAD];
__device__ float g_V[Nn * Hh * Ll * PAD];

__device__ __forceinline__ float ex2f(float x) {
    float y;
    asm("ex2.approx.ftz.f32 %0, %1;" : "=f"(y) : "f"(x));
    return y;
}

// ---------------------------------------------------------------------------
// Projection: q/k/v = xf @ W^T + b, reshaped to [N, H, L, PAD].
// Grid: (128 row-blocks of 64, 3 matrices). 256 threads.
// SMEM: Wt[112][113] (transposed, padded) + As[64][113] + bias[112] ~ 80 KB.
// Thread (rr, oc): rr = tid>>4 picks 4 rows, oc = tid&15 picks one head (7 outs).
// ---------------------------------------------------------------------------
__global__ __launch_bounds__(256) void proj_kernel(
    const float* __restrict__ x,
    const float* __restrict__ Wq, const float* __restrict__ bq,
    const float* __restrict__ Wk, const float* __restrict__ bk,
    const float* __restrict__ Wv, const float* __restrict__ bv)
{
    extern __shared__ float sm[];
    float* Wt = sm;                    // [112][113]: Wt[i*113+o] = W[o][i]
    float* As = sm + 112 * 113;        // [64][113]
    float* bs = As + 64 * 113;         // [112]

    const int z = blockIdx.y;
    const float* W = (z == 0) ? Wq : ((z == 1) ? Wk : Wv);
    const float* b = (z == 0) ? bq : ((z == 1) ? bk : bv);
    float* dst     = (z == 0) ? g_Q : ((z == 1) ? g_K : g_V);
    // Fold softmax scale (1/sqrt(L)=1/32) and log2(e) into Q.
    const float scale = (z == 0) ? (1.4426950408889634f / 32.0f) : 1.0f;

    const int tid  = threadIdx.x;
    const int row0 = blockIdx.x * 64;

    // Stage W transposed (conflict-free reads later: 7*oc spans all banks).
    for (int e = tid; e < SZ * SZ; e += 256) {
        int o = e / SZ, i = e - o * SZ;
        Wt[i * 113 + o] = W[e];
    }
    // Stage xf tile: xf[row, i] = x[n, i/7, l, i%7]
    for (int e = tid; e < 64 * SZ; e += 256) {
        int r = e / SZ, i = e - r * SZ;
        int row = row0 + r;
        int n = row >> 10, l = row & 1023;
        int c = i / Dd, dd = i - c * Dd;
        As[r * 113 + i] = x[(((n * Cc + c) << 10) + l) * Dd + dd];
    }
    if (tid < SZ) bs[tid] = b[tid];
    __syncthreads();

    const int rr = tid >> 4;   // 0..15 -> rows rr*4 .. rr*4+3
    const int oc = tid & 15;   // head index 0..15 -> outputs oc*7 .. oc*7+6

    float acc[4][7];
#pragma unroll
    for (int k = 0; k < 4; ++k)
#pragma unroll
        for (int j = 0; j < 7; ++j) acc[k][j] = 0.0f;

#pragma unroll 4
    for (int i = 0; i < SZ; ++i) {
        float w[7];
#pragma unroll
        for (int j = 0; j < 7; ++j) w[j] = Wt[i * 113 + oc * 7 + j];
#pragma unroll
        for (int k = 0; k < 4; ++k) {
            float a = As[(rr * 4 + k) * 113 + i];
#pragma unroll
            for (int j = 0; j < 7; ++j) acc[k][j] = fmaf(a, w[j], acc[k][j]);
        }
    }

#pragma unroll
    for (int k = 0; k < 4; ++k) {
        int row = row0 + rr * 4 + k;
        int n = row >> 10, l = row & 1023;
        float4* p = (float4*)(dst + (((n * Hh + oc) << 10) + l) * PAD);
        float r0 = (acc[k][0] + bs[oc * 7 + 0]) * scale;
        float r1 = (acc[k][1] + bs[oc * 7 + 1]) * scale;
        float r2 = (acc[k][2] + bs[oc * 7 + 2]) * scale;
        float r3 = (acc[k][3] + bs[oc * 7 + 3]) * scale;
        float r4 = (acc[k][4] + bs[oc * 7 + 4]) * scale;
        float r5 = (acc[k][5] + bs[oc * 7 + 5]) * scale;
        float r6 = (acc[k][6] + bs[oc * 7 + 6]) * scale;
        p[0] = make_float4(r0, r1, r2, r3);
        p[1] = make_float4(r4, r5, r6, 0.0f);
    }
}

// ---------------------------------------------------------------------------
// Fused attention. 1024 CTAs: CTA b handles bh = b>>3, query rows
// (b&7)*128 .. +127 (one row per thread, 128 threads). Full K and V for the
// bh live in SMEM (64 KB); occ = 3 CTAs/SM so all 148 SMs stay busy
// (makespan 7/8 of the old 128-CTA layout).
// Single-pass softmax (|score| small -> no max subtraction).
// Q pre-scaled by log2(e)/32, so weight = ex2(q.k).
// ---------------------------------------------------------------------------
__global__ __launch_bounds__(128) void attn_kernel(float* __restrict__ out)
{
    extern __shared__ float sm[];
    float4* K4 = (float4*)sm;          // 2048 float4 = 32 KB
    float4* V4 = K4 + 2048;            // 2048 float4 = 32 KB

    const int b   = blockIdx.x;
    const int bh  = b >> 3;
    const int row = ((b & 7) << 7) + threadIdx.x;
    const int tid = threadIdx.x;

    const float4* gK4 = (const float4*)g_K + bh * 2048;
    const float4* gV4 = (const float4*)g_V + bh * 2048;
    for (int e = tid; e < 2048; e += 128) {
        K4[e] = gK4[e];
        V4[e] = gV4[e];
    }

    float q[7];
    {
        const float4* qp = (const float4*)(g_Q + (bh * Ll + row) * PAD);
        float4 qa = qp[0], qb = qp[1];
        q[0] = qa.x; q[1] = qa.y; q[2] = qa.z; q[3] = qa.w;
        q[4] = qb.x; q[5] = qb.y; q[6] = qb.z;
    }
    __syncthreads();

    float ssum = 0.0f;
    float acc[7];
#pragma unroll
    for (int j = 0; j < 7; ++j) acc[j] = 0.0f;

#pragma unroll 4
    for (int jj = 0; jj < Ll; ++jj) {
        float4 ka = K4[2 * jj], kb = K4[2 * jj + 1];
        float4 va = V4[2 * jj], vb = V4[2 * jj + 1];
        float s = q[0] * ka.x;
        s = fmaf(q[1], ka.y, s);
        s = fmaf(q[2], ka.z, s);
        s = fmaf(q[3], ka.w, s);
        s = fmaf(q[4], kb.x, s);
        s = fmaf(q[5], kb.y, s);
        s = fmaf(q[6], kb.z, s);
        float e = ex2f(s);
        ssum += e;
        acc[0] = fmaf(e, va.x, acc[0]);
        acc[1] = fmaf(e, va.y, acc[1]);
        acc[2] = fmaf(e, va.z, acc[2]);
        acc[3] = fmaf(e, va.w, acc[3]);
        acc[4] = fmaf(e, vb.x, acc[4]);
        acc[5] = fmaf(e, vb.y, acc[5]);
        acc[6] = fmaf(e, vb.z, acc[6]);
    }

    float inv = 1.0f / ssum;
    float* p = out + (bh * Ll + row) * Dd;
#pragma unroll
    for (int j = 0; j < 7; ++j) p[j] = acc[j] * inv;
}

extern "C" void kernel_launch(void* const* d_in, const int* in_sizes, int n_in,
                              void* d_out, int out_size)
{
    const float* x  = (const float*)d_in[0];
    const float* Wq = (const float*)d_in[1];
    const float* bq = (const float*)d_in[2];
    const float* Wk = (const float*)d_in[3];
    const float* bk = (const float*)d_in[4];
    const float* Wv = (const float*)d_in[5];
    const float* bv = (const float*)d_in[6];

    cudaFuncSetAttribute(proj_kernel, cudaFuncAttributeMaxDynamicSharedMemorySize, 98304);
    cudaFuncSetAttribute(attn_kernel, cudaFuncAttributeMaxDynamicSharedMemorySize, 65536);

    proj_kernel<<<dim3(128, 3, 1), 256, 98304>>>(x, Wq, bq, Wk, bk, Wv, bv);
    attn_kernel<<<Nn * Hh * 8, 128, 65536>>>((float*)d_out);
}

// round 4
// speedup vs baseline: 1.5182x; 1.5182x over previous
#include <cuda_runtime.h>

// Problem constants
#define Nn 8
#define Cc 16
#define Ll 1024
#define Dd 7
#define Hh 16
#define SZ 112      // C*D = H*dh
#define PAD 8       // padded head_dim for float4 access

// Scratch: Q/K/V in [N, H, L, PAD] layout. Q pre-scaled by log2(e)/32.
__device__ float g_Q[Nn * Hh * Ll * PAD];
__device__ float g_K[Nn * Hh * Ll * PAD];
__device__ float g_V[Nn * Hh * Ll * PAD];

__device__ __forceinline__ float ex2f(float x) {
    float y;
    asm("ex2.approx.ftz.f32 %0, %1;" : "=f"(y) : "f"(x));
    return y;
}

// ---------------------------------------------------------------------------
// Projection: q/k/v = xf @ W^T + b, reshaped to [N, H, L, PAD].
// Grid: (128 row-blocks of 64, 3 matrices). 256 threads. ~80 KB smem.
// W staged once per 64 rows (half the staging cost of 32-row tiles).
// ---------------------------------------------------------------------------
__global__ __launch_bounds__(256) void proj_kernel(
    const float* __restrict__ x,
    const float* __restrict__ Wq, const float* __restrict__ bq,
    const float* __restrict__ Wk, const float* __restrict__ bk,
    const float* __restrict__ Wv, const float* __restrict__ bv)
{
    extern __shared__ float sm[];
    float* Wt = sm;                    // [112][113]: Wt[i*113+o] = W[o][i]
    float* As = sm + 112 * 113;        // [64][113]
    float* bs = As + 64 * 113;         // [112]

    const int z = blockIdx.y;
    const float* W = (z == 0) ? Wq : ((z == 1) ? Wk : Wv);
    const float* b = (z == 0) ? bq : ((z == 1) ? bk : bv);
    float* dst     = (z == 0) ? g_Q : ((z == 1) ? g_K : g_V);
    // Fold softmax scale (1/sqrt(L)=1/32) and log2(e) into Q.
    const float scale = (z == 0) ? (1.4426950408889634f / 32.0f) : 1.0f;

    const int tid  = threadIdx.x;
    const int row0 = blockIdx.x * 64;

    // Stage W transposed (conflict-free reads later: 7*oc spans all banks).
    for (int e = tid; e < SZ * SZ; e += 256) {
        int o = e / SZ, i = e - o * SZ;
        Wt[i * 113 + o] = W[e];
    }
    // Stage xf tile: xf[row, i] = x[n, i/7, l, i%7]
    for (int e = tid; e < 64 * SZ; e += 256) {
        int r = e / SZ, i = e - r * SZ;
        int row = row0 + r;
        int n = row >> 10, l = row & 1023;
        int c = i / Dd, dd = i - c * Dd;
        As[r * 113 + i] = x[(((n * Cc + c) << 10) + l) * Dd + dd];
    }
    if (tid < SZ) bs[tid] = b[tid];
    __syncthreads();

    const int rr = tid >> 4;   // 0..15 -> rows rr*4 .. rr*4+3
    const int oc = tid & 15;   // head index 0..15 -> outputs oc*7 .. oc*7+6

    float acc[4][7];
#pragma unroll
    for (int k = 0; k < 4; ++k)
#pragma unroll
        for (int j = 0; j < 7; ++j) acc[k][j] = 0.0f;

#pragma unroll 4
    for (int i = 0; i < SZ; ++i) {
        float w[7];
#pragma unroll
        for (int j = 0; j < 7; ++j) w[j] = Wt[i * 113 + oc * 7 + j];
#pragma unroll
        for (int k = 0; k < 4; ++k) {
            float a = As[(rr * 4 + k) * 113 + i];
#pragma unroll
            for (int j = 0; j < 7; ++j) acc[k][j] = fmaf(a, w[j], acc[k][j]);
        }
    }

#pragma unroll
    for (int k = 0; k < 4; ++k) {
        int row = row0 + rr * 4 + k;
        int n = row >> 10, l = row & 1023;
        float4* p = (float4*)(dst + (((n * Hh + oc) << 10) + l) * PAD);
        float r0 = (acc[k][0] + bs[oc * 7 + 0]) * scale;
        float r1 = (acc[k][1] + bs[oc * 7 + 1]) * scale;
        float r2 = (acc[k][2] + bs[oc * 7 + 2]) * scale;
        float r3 = (acc[k][3] + bs[oc * 7 + 3]) * scale;
        float r4 = (acc[k][4] + bs[oc * 7 + 4]) * scale;
        float r5 = (acc[k][5] + bs[oc * 7 + 5]) * scale;
        float r6 = (acc[k][6] + bs[oc * 7 + 6]) * scale;
        p[0] = make_float4(r0, r1, r2, r3);
        p[1] = make_float4(r4, r5, r6, 0.0f);
    }
}

// ---------------------------------------------------------------------------
// Fused attention (R1 config — measured FFMA-dispatch-bound at 111.8us).
// One CTA per (n, h). K and V (32 KB each) in SMEM. 256 threads; thread owns
// rows {tid, tid+256, tid+512, tid+768} (4 rows amortize each K/V LDS).
// Single-pass softmax (no max subtraction: |score| <~ 2 so exp is safe).
// Q pre-scaled by log2(e)/32, so weight = ex2(q.k).
// ---------------------------------------------------------------------------
__global__ __launch_bounds__(256) void attn_kernel(float* __restrict__ out)
{
    extern __shared__ float sm[];
    float4* K4 = (float4*)sm;          // 2048 float4
    float4* V4 = K4 + 2048;            // 2048 float4

    const int bh  = blockIdx.x;        // n*16 + h
    const int tid = threadIdx.x;

    const float4* gK4 = (const float4*)g_K + bh * 2048;
    const float4* gV4 = (const float4*)g_V + bh * 2048;
    for (int e = tid; e < 2048; e += 256) {
        K4[e] = gK4[e];
        V4[e] = gV4[e];
    }

    float q[4][7];
#pragma unroll
    for (int k = 0; k < 4; ++k) {
        const float4* qp = (const float4*)(g_Q + (bh * Ll + tid + 256 * k) * PAD);
        float4 qa = qp[0], qb = qp[1];
        q[k][0] = qa.x; q[k][1] = qa.y; q[k][2] = qa.z; q[k][3] = qa.w;
        q[k][4] = qb.x; q[k][5] = qb.y; q[k][6] = qb.z;
    }
    __syncthreads();

    float ssum[4] = {0.f, 0.f, 0.f, 0.f};
    float acc[4][7];
#pragma unroll
    for (int k = 0; k < 4; ++k)
#pragma unroll
        for (int j = 0; j < 7; ++j) acc[k][j] = 0.0f;

#pragma unroll 2
    for (int jj = 0; jj < Ll; ++jj) {
        float4 ka = K4[2 * jj], kb = K4[2 * jj + 1];
        float4 va = V4[2 * jj], vb = V4[2 * jj + 1];
#pragma unroll
        for (int k = 0; k < 4; ++k) {
            float s = q[k][0] * ka.x;
            s = fmaf(q[k][1], ka.y, s);
            s = fmaf(q[k][2], ka.z, s);
            s = fmaf(q[k][3], ka.w, s);
            s = fmaf(q[k][4], kb.x, s);
            s = fmaf(q[k][5], kb.y, s);
            s = fmaf(q[k][6], kb.z, s);
            float e = ex2f(s);
            ssum[k] += e;
            acc[k][0] = fmaf(e, va.x, acc[k][0]);
            acc[k][1] = fmaf(e, va.y, acc[k][1]);
            acc[k][2] = fmaf(e, va.z, acc[k][2]);
            acc[k][3] = fmaf(e, va.w, acc[k][3]);
            acc[k][4] = fmaf(e, vb.x, acc[k][4]);
            acc[k][5] = fmaf(e, vb.y, acc[k][5]);
            acc[k][6] = fmaf(e, vb.z, acc[k][6]);
        }
    }

#pragma unroll
    for (int k = 0; k < 4; ++k) {
        int row = tid + 256 * k;
        float inv = 1.0f / ssum[k];
        float* p = out + (bh * Ll + row) * Dd;
#pragma unroll
        for (int j = 0; j < 7; ++j) p[j] = acc[k][j] * inv;
    }
}

extern "C" void kernel_launch(void* const* d_in, const int* in_sizes, int n_in,
                              void* d_out, int out_size)
{
    const float* x  = (const float*)d_in[0];
    const float* Wq = (const float*)d_in[1];
    const float* bq = (const float*)d_in[2];
    const float* Wk = (const float*)d_in[3];
    const float* bk = (const float*)d_in[4];
    const float* Wv = (const float*)d_in[5];
    const float* bv = (const float*)d_in[6];

    cudaFuncSetAttribute(proj_kernel, cudaFuncAttributeMaxDynamicSharedMemorySize, 98304);
    cudaFuncSetAttribute(attn_kernel, cudaFuncAttributeMaxDynamicSharedMemorySize, 65536);

    proj_kernel<<<dim3(128, 3, 1), 256, 98304>>>(x, Wq, bq, Wk, bk, Wv, bv);
    attn_kernel<<<Nn * Hh, 256, 65536>>>((float*)d_out);
}

// round 5
// speedup vs baseline: 1.5197x; 1.0009x over previous
#include <cuda_runtime.h>

// Problem constants
#define Nn 8
#define Cc 16
#define Ll 1024
#define Dd 7
#define Hh 16
#define SZ 112      // C*D = H*dh
#define PAD 8       // padded head_dim for float4 access

// Scratch: Q/K/V in [N, H, L, PAD] layout. Q pre-scaled by log2(e)/32.
__device__ float g_Q[Nn * Hh * Ll * PAD];
__device__ float g_K[Nn * Hh * Ll * PAD];
__device__ float g_V[Nn * Hh * Ll * PAD];

__device__ __forceinline__ float ex2f(float x) {
    float y;
    asm("ex2.approx.ftz.f32 %0, %1;" : "=f"(y) : "f"(x));
    return y;
}

// ---------------------------------------------------------------------------
// Projection: q/k/v = xf @ W^T + b, reshaped to [N, H, L, PAD].
// Grid: (128 row-blocks of 64, 3 matrices). 256 threads. ~80 KB smem.
// W staged once per 64 rows (half the staging cost of 32-row tiles).
// ---------------------------------------------------------------------------
__global__ __launch_bounds__(256) void proj_kernel(
    const float* __restrict__ x,
    const float* __restrict__ Wq, const float* __restrict__ bq,
    const float* __restrict__ Wk, const float* __restrict__ bk,
    const float* __restrict__ Wv, const float* __restrict__ bv)
{
    extern __shared__ float sm[];
    float* Wt = sm;                    // [112][113]: Wt[i*113+o] = W[o][i]
    float* As = sm + 112 * 113;        // [64][113]
    float* bs = As + 64 * 113;         // [112]

    const int z = blockIdx.y;
    const float* W = (z == 0) ? Wq : ((z == 1) ? Wk : Wv);
    const float* b = (z == 0) ? bq : ((z == 1) ? bk : bv);
    float* dst     = (z == 0) ? g_Q : ((z == 1) ? g_K : g_V);
    // Fold softmax scale (1/sqrt(L)=1/32) and log2(e) into Q.
    const float scale = (z == 0) ? (1.4426950408889634f / 32.0f) : 1.0f;

    const int tid  = threadIdx.x;
    const int row0 = blockIdx.x * 64;

    // Stage W transposed (conflict-free reads later: 7*oc spans all banks).
    for (int e = tid; e < SZ * SZ; e += 256) {
        int o = e / SZ, i = e - o * SZ;
        Wt[i * 113 + o] = W[e];
    }
    // Stage xf tile: xf[row, i] = x[n, i/7, l, i%7]
    for (int e = tid; e < 64 * SZ; e += 256) {
        int r = e / SZ, i = e - r * SZ;
        int row = row0 + r;
        int n = row >> 10, l = row & 1023;
        int c = i / Dd, dd = i - c * Dd;
        As[r * 113 + i] = x[(((n * Cc + c) << 10) + l) * Dd + dd];
    }
    if (tid < SZ) bs[tid] = b[tid];
    __syncthreads();

    const int rr = tid >> 4;   // 0..15 -> rows rr*4 .. rr*4+3
    const int oc = tid & 15;   // head index 0..15 -> outputs oc*7 .. oc*7+6

    float acc[4][7];
#pragma unroll
    for (int k = 0; k < 4; ++k)
#pragma unroll
        for (int j = 0; j < 7; ++j) acc[k][j] = 0.0f;

#pragma unroll 4
    for (int i = 0; i < SZ; ++i) {
        float w[7];
#pragma unroll
        for (int j = 0; j < 7; ++j) w[j] = Wt[i * 113 + oc * 7 + j];
#pragma unroll
        for (int k = 0; k < 4; ++k) {
            float a = As[(rr * 4 + k) * 113 + i];
#pragma unroll
            for (int j = 0; j < 7; ++j) acc[k][j] = fmaf(a, w[j], acc[k][j]);
        }
    }

#pragma unroll
    for (int k = 0; k < 4; ++k) {
        int row = row0 + rr * 4 + k;
        int n = row >> 10, l = row & 1023;
        float4* p = (float4*)(dst + (((n * Hh + oc) << 10) + l) * PAD);
        float r0 = (acc[k][0] + bs[oc * 7 + 0]) * scale;
        float r1 = (acc[k][1] + bs[oc * 7 + 1]) * scale;
        float r2 = (acc[k][2] + bs[oc * 7 + 2]) * scale;
        float r3 = (acc[k][3] + bs[oc * 7 + 3]) * scale;
        float r4 = (acc[k][4] + bs[oc * 7 + 4]) * scale;
        float r5 = (acc[k][5] + bs[oc * 7 + 5]) * scale;
        float r6 = (acc[k][6] + bs[oc * 7 + 6]) * scale;
        p[0] = make_float4(r0, r1, r2, r3);
        p[1] = make_float4(r4, r5, r6, 0.0f);
    }
}

// ---------------------------------------------------------------------------
// Fused attention (R1 config — measured FFMA-dispatch-bound at 111.8us).
// One CTA per (n, h). K and V (32 KB each) in SMEM. 256 threads; thread owns
// rows {tid, tid+256, tid+512, tid+768} (4 rows amortize each K/V LDS).
// Single-pass softmax (no max subtraction: |score| <~ 2 so exp is safe).
// Q pre-scaled by log2(e)/32, so weight = ex2(q.k).
// ---------------------------------------------------------------------------
__global__ __launch_bounds__(256) void attn_kernel(float* __restrict__ out)
{
    extern __shared__ float sm[];
    float4* K4 = (float4*)sm;          // 2048 float4
    float4* V4 = K4 + 2048;            // 2048 float4

    const int bh  = blockIdx.x;        // n*16 + h
    const int tid = threadIdx.x;

    const float4* gK4 = (const float4*)g_K + bh * 2048;
    const float4* gV4 = (const float4*)g_V + bh * 2048;
    for (int e = tid; e < 2048; e += 256) {
        K4[e] = gK4[e];
        V4[e] = gV4[e];
    }

    float q[4][7];
#pragma unroll
    for (int k = 0; k < 4; ++k) {
        const float4* qp = (const float4*)(g_Q + (bh * Ll + tid + 256 * k) * PAD);
        float4 qa = qp[0], qb = qp[1];
        q[k][0] = qa.x; q[k][1] = qa.y; q[k][2] = qa.z; q[k][3] = qa.w;
        q[k][4] = qb.x; q[k][5] = qb.y; q[k][6] = qb.z;
    }
    __syncthreads();

    float ssum[4] = {0.f, 0.f, 0.f, 0.f};
    float acc[4][7];
#pragma unroll
    for (int k = 0; k < 4; ++k)
#pragma unroll
        for (int j = 0; j < 7; ++j) acc[k][j] = 0.0f;

#pragma unroll 2
    for (int jj = 0; jj < Ll; ++jj) {
        float4 ka = K4[2 * jj], kb = K4[2 * jj + 1];
        float4 va = V4[2 * jj], vb = V4[2 * jj + 1];
#pragma unroll
        for (int k = 0; k < 4; ++k) {
            float s = q[k][0] * ka.x;
            s = fmaf(q[k][1], ka.y, s);
            s = fmaf(q[k][2], ka.z, s);
            s = fmaf(q[k][3], ka.w, s);
            s = fmaf(q[k][4], kb.x, s);
            s = fmaf(q[k][5], kb.y, s);
            s = fmaf(q[k][6], kb.z, s);
            float e = ex2f(s);
            ssum[k] += e;
            acc[k][0] = fmaf(e, va.x, acc[k][0]);
            acc[k][1] = fmaf(e, va.y, acc[k][1]);
            acc[k][2] = fmaf(e, va.z, acc[k][2]);
            acc[k][3] = fmaf(e, va.w, acc[k][3]);
            acc[k][4] = fmaf(e, vb.x, acc[k][4]);
            acc[k][5] = fmaf(e, vb.y, acc[k][5]);
            acc[k][6] = fmaf(e, vb.z, acc[k][6]);
        }
    }

#pragma unroll
    for (int k = 0; k < 4; ++k) {
        int row = tid + 256 * k;
        float inv = 1.0f / ssum[k];
        float* p = out + (bh * Ll + row) * Dd;
#pragma unroll
        for (int j = 0; j < 7; ++j) p[j] = acc[k][j] * inv;
    }
}

extern "C" void kernel_launch(void* const* d_in, const int* in_sizes, int n_in,
                              void* d_out, int out_size)
{
    const float* x  = (const float*)d_in[0];
    const float* Wq = (const float*)d_in[1];
    const float* bq = (const float*)d_in[2];
    const float* Wk = (const float*)d_in[3];
    const float* bk = (const float*)d_in[4];
    const float* Wv = (const float*)d_in[5];
    const float* bv = (const float*)d_in[6];

    cudaFuncSetAttribute(proj_kernel, cudaFuncAttributeMaxDynamicSharedMemorySize, 98304);
    cudaFuncSetAttribute(attn_kernel, cudaFuncAttributeMaxDynamicSharedMemorySize, 65536);

    proj_kernel<<<dim3(128, 3, 1), 256, 98304>>>(x, Wq, bq, Wk, bk, Wv, bv);
    attn_kernel<<<Nn * Hh, 256, 65536>>>((float*)d_out);
}

// round 7
// speedup vs baseline: 2.0858x; 1.3726x over previous
#include <cuda_runtime.h>
#include <cstdint>

#define Nn 8
#define Cc 16
#define Ll 1024
#define Dd 7
#define Hh 16
#define SZ 112
#define PAD 8

// Scratch: Q/K/V in [bh, l, 8] fp32, values pre-rounded to tf32 (rna).
// Q pre-scaled by log2(e)/32. V pad dim = 1.0 (gives softmax denom via MMA).
__device__ float g_Q[Nn * Hh * Ll * PAD];
__device__ float g_K[Nn * Hh * Ll * PAD];
__device__ float g_V[Nn * Hh * Ll * PAD];

__device__ __forceinline__ float ex2f(float x) {
    float y; asm("ex2.approx.ftz.f32 %0, %1;" : "=f"(y) : "f"(x)); return y;
}
__device__ __forceinline__ float tf32r(float x) {
    uint32_t u; asm("cvt.rna.tf32.f32 %0, %1;" : "=r"(u) : "f"(x));
    return __uint_as_float(u);
}
// D = A(16x8) @ B(8x8) + C, tf32 inputs, fp32 accum.
__device__ __forceinline__ void mma16n8k8(float& d0, float& d1, float& d2, float& d3,
                                          uint32_t a0, uint32_t a1, uint32_t a2, uint32_t a3,
                                          uint32_t b0, uint32_t b1) {
    asm volatile(
        "mma.sync.aligned.m16n8k8.row.col.f32.tf32.tf32.f32 "
        "{%0,%1,%2,%3}, {%4,%5,%6,%7}, {%8,%9}, {%0,%1,%2,%3};"
        : "+f"(d0), "+f"(d1), "+f"(d2), "+f"(d3)
        : "r"(a0), "r"(a1), "r"(a2), "r"(a3), "r"(b0), "r"(b1));
}

// ---------------------------------------------------------------------------
// Projection: q/k/v = xf @ W^T + b -> [bh, l, 8], tf32-rounded.
// ---------------------------------------------------------------------------
__global__ __launch_bounds__(256) void proj_kernel(
    const float* __restrict__ x,
    const float* __restrict__ Wq, const float* __restrict__ bq,
    const float* __restrict__ Wk, const float* __restrict__ bk,
    const float* __restrict__ Wv, const float* __restrict__ bv)
{
    extern __shared__ float sm[];
    float* Wt = sm;
    float* As = sm + 112 * 113;
    float* bs = As + 64 * 113;

    const int z = blockIdx.y;
    const float* W = (z == 0) ? Wq : ((z == 1) ? Wk : Wv);
    const float* b = (z == 0) ? bq : ((z == 1) ? bk : bv);
    float* dst     = (z == 0) ? g_Q : ((z == 1) ? g_K : g_V);
    const float scale = (z == 0) ? (1.4426950408889634f / 32.0f) : 1.0f;
    const float padv  = (z == 2) ? 1.0f : 0.0f;

    const int tid  = threadIdx.x;
    const int row0 = blockIdx.x * 64;

    for (int e = tid; e < SZ * SZ; e += 256) {
        int o = e / SZ, i = e - o * SZ;
        Wt[i * 113 + o] = W[e];
    }
    for (int e = tid; e < 64 * SZ; e += 256) {
        int r = e / SZ, i = e - r * SZ;
        int row = row0 + r;
        int n = row >> 10, l = row & 1023;
        int c = i / Dd, dd = i - c * Dd;
        As[r * 113 + i] = x[(((n * Cc + c) << 10) + l) * Dd + dd];
    }
    if (tid < SZ) bs[tid] = b[tid];
    __syncthreads();

    const int rr = tid >> 4, oc = tid & 15;
    float acc[4][7];
#pragma unroll
    for (int k = 0; k < 4; ++k)
#pragma unroll
        for (int j = 0; j < 7; ++j) acc[k][j] = 0.0f;

#pragma unroll 4
    for (int i = 0; i < SZ; ++i) {
        float w[7];
#pragma unroll
        for (int j = 0; j < 7; ++j) w[j] = Wt[i * 113 + oc * 7 + j];
#pragma unroll
        for (int k = 0; k < 4; ++k) {
            float a = As[(rr * 4 + k) * 113 + i];
#pragma unroll
            for (int j = 0; j < 7; ++j) acc[k][j] = fmaf(a, w[j], acc[k][j]);
        }
    }
#pragma unroll
    for (int k = 0; k < 4; ++k) {
        int row = row0 + rr * 4 + k;
        int n = row >> 10, l = row & 1023;
        float4* p = (float4*)(dst + (((n * Hh + oc) << 10) + l) * PAD);
        float r0 = tf32r((acc[k][0] + bs[oc * 7 + 0]) * scale);
        float r1 = tf32r((acc[k][1] + bs[oc * 7 + 1]) * scale);
        float r2 = tf32r((acc[k][2] + bs[oc * 7 + 2]) * scale);
        float r3 = tf32r((acc[k][3] + bs[oc * 7 + 3]) * scale);
        float r4 = tf32r((acc[k][4] + bs[oc * 7 + 4]) * scale);
        float r5 = tf32r((acc[k][5] + bs[oc * 7 + 5]) * scale);
        float r6 = tf32r((acc[k][6] + bs[oc * 7 + 6]) * scale);
        p[0] = make_float4(r0, r1, r2, r3);
        p[1] = make_float4(r4, r5, r6, padv);
    }
}

// ---------------------------------------------------------------------------
// Warp-MMA attention (m16n8k8 tf32). CTA = (qtile, bh): 128 queries x 1024
// keys; 8 warps, each owns 16 query rows. K^T [8][1032] and V [1024][8]
// (pad dim = 1) staged in SMEM (~64 KB, 2 CTAs/SM). Per 8-key chunk:
// 1 QK MMA -> ex2 x4 -> shfl relayout -> 1 AV MMA (accumulates out + denom).
// ---------------------------------------------------------------------------
__global__ __launch_bounds__(256, 2) void attn_kernel(float* __restrict__ out)
{
    extern __shared__ char smem[];
    float* KT = (float*)smem;               // [8][1032] floats (33024 B)
    float* Vs = (float*)(smem + 33024);     // [1024][8] floats (32768 B)

    const int tid = threadIdx.x;
    const int wid = tid >> 5, lid = tid & 31;
    const int g = lid >> 2, t = lid & 3;
    const int qt = blockIdx.x;
    const int bh = blockIdx.y;

    // Stage K^T (conflict-free B-frag reads: bank = t*8+g, all distinct).
    const float* gK = g_K + bh * Ll * PAD;
    for (int e = tid; e < 8192; e += 256) {
        int key = e >> 3, dim = e & 7;
        KT[dim * 1032 + key] = gK[e];
    }
    // Stage V (row-major [key][8]; B-frag reads conflict-free).
    {
        const float4* gV4 = (const float4*)(g_V + bh * Ll * PAD);
        float4* V4 = (float4*)Vs;
        for (int e = tid; e < 2048; e += 256) V4[e] = gV4[e];
    }

    // Q A-fragment (rows wid*16 + {g, g+8}, k-dims {t, t+4}).
    const float* qb = g_Q + (bh * Ll + qt * 128 + wid * 16) * PAD;
    const uint32_t qa0 = __float_as_uint(qb[g * 8 + t]);
    const uint32_t qa1 = __float_as_uint(qb[(g + 8) * 8 + t]);
    const uint32_t qa2 = __float_as_uint(qb[g * 8 + t + 4]);
    const uint32_t qa3 = __float_as_uint(qb[(g + 8) * 8 + t + 4]);
    __syncthreads();

    float o0 = 0.f, o1 = 0.f, o2 = 0.f, o3 = 0.f;   // out frag (cols=dims, col7=denom)

    const int sA = (lid & ~3) | (t >> 1);   // relayout source lanes
    const int sB = sA + 2;
    const bool odd = (t & 1);

#pragma unroll 4
    for (int c = 0; c < 128; ++c) {
        const int k0 = c * 8;
        // QK B-frag: B[k=dim][n=key]
        uint32_t kb0 = __float_as_uint(KT[t * 1032 + k0 + g]);
        uint32_t kb1 = __float_as_uint(KT[(t + 4) * 1032 + k0 + g]);
        float s0 = 0.f, s1 = 0.f, s2 = 0.f, s3 = 0.f;
        mma16n8k8(s0, s1, s2, s3, qa0, qa1, qa2, qa3, kb0, kb1);

        // softmax weights (log2-domain scores; no max-sub needed, |s| small)
        float e0 = ex2f(s0), e1 = ex2f(s1), e2 = ex2f(s2), e3 = ex2f(s3);

        // C-frag (cols 2t,2t+1) -> A-frag (cols t,t+4) relayout
        float v00 = __shfl_sync(0xffffffffu, e0, sA);
        float v01 = __shfl_sync(0xffffffffu, e1, sA);
        float v02 = __shfl_sync(0xffffffffu, e0, sB);
        float v03 = __shfl_sync(0xffffffffu, e1, sB);
        float v10 = __shfl_sync(0xffffffffu, e2, sA);
        float v11 = __shfl_sync(0xffffffffu, e3, sA);
        float v12 = __shfl_sync(0xffffffffu, e2, sB);
        float v13 = __shfl_sync(0xffffffffu, e3, sB);
        uint32_t wa0 = __float_as_uint(odd ? v01 : v00);
        uint32_t wa2 = __float_as_uint(odd ? v03 : v02);
        uint32_t wa1 = __float_as_uint(odd ? v11 : v10);
        uint32_t wa3 = __float_as_uint(odd ? v13 : v12);

        // AV B-frag: B[k=key][n=dim]
        uint32_t vb0 = __float_as_uint(Vs[(k0 + t) * 8 + g]);
        uint32_t vb1 = __float_as_uint(Vs[(k0 + t + 4) * 8 + g]);
        mma16n8k8(o0, o1, o2, o3, wa0, wa1, wa2, wa3, vb0, vb1);
    }

    // Denominator = col 7, held by lane (g<<2)|3 (regs o1 row g, o3 row g+8).
    float sum0 = __shfl_sync(0xffffffffu, o1, (lid & ~3) | 3);
    float sum1 = __shfl_sync(0xffffffffu, o3, (lid & ~3) | 3);
    float i0 = 1.0f / sum0, i1 = 1.0f / sum1;

    const int row = bh * Ll + qt * 128 + wid * 16 + g;
    float* p0 = out + row * Dd;
    float* p1 = out + (row + 8) * Dd;
    p0[2 * t] = o0 * i0;
    p1[2 * t] = o2 * i1;
    if (t < 3) {
        p0[2 * t + 1] = o1 * i0;
        p1[2 * t + 1] = o3 * i1;
    }
}

extern "C" void kernel_launch(void* const* d_in, const int* in_sizes, int n_in,
                              void* d_out, int out_size)
{
    const float* x  = (const float*)d_in[0];
    const float* Wq = (const float*)d_in[1];
    const float* bq = (const float*)d_in[2];
    const float* Wk = (const float*)d_in[3];
    const float* bk = (const float*)d_in[4];
    const float* Wv = (const float*)d_in[5];
    const float* bv = (const float*)d_in[6];

    cudaFuncSetAttribute(proj_kernel, cudaFuncAttributeMaxDynamicSharedMemorySize, 98304);
    cudaFuncSetAttribute(attn_kernel, cudaFuncAttributeMaxDynamicSharedMemorySize, 65792);

    proj_kernel<<<dim3(128, 3, 1), 256, 98304>>>(x, Wq, bq, Wk, bk, Wv, bv);
    attn_kernel<<<dim3(8, 128, 1), 256, 65792>>>((float*)d_out);
}

// round 9
// speedup vs baseline: 3.2388x; 1.5528x over previous
#include <cuda_runtime.h>
#include <cuda_fp16.h>
#include <cstdint>

#define Nn 8
#define Cc 16
#define Ll 1024
#define Dd 7
#define Hh 16
#define SZ 112
#define PAD 8

// Scratch: Q/K in [bh, l, 8] fp32 tf32-rounded (Q pre-scaled by log2(e)/32);
// V in [bh, l, 8] fp32 with pad dim = 1.0 (becomes softmax denom via MMA).
__device__ float g_Q[Nn * Hh * Ll * PAD];
__device__ float g_K[Nn * Hh * Ll * PAD];
__device__ float g_V[Nn * Hh * Ll * PAD];

__device__ __forceinline__ float ex2f(float x) {
    float y; asm("ex2.approx.ftz.f32 %0, %1;" : "=f"(y) : "f"(x)); return y;
}
__device__ __forceinline__ float tf32r(float x) {
    uint32_t u; asm("cvt.rna.tf32.f32 %0, %1;" : "=r"(u) : "f"(x));
    return __uint_as_float(u);
}
// Pack two fp32 into one f16x2 register (lo = a, hi = b).
__device__ __forceinline__ uint32_t f16x2(float a, float b) {
    uint32_t r;
    asm("cvt.rn.f16x2.f32 %0, %1, %2;" : "=r"(r) : "f"(b), "f"(a));
    return r;
}
// D += A(16x8) @ B(8x8), tf32 in, fp32 accum.
__device__ __forceinline__ void mma_tf32_k8(float& d0, float& d1, float& d2, float& d3,
                                            uint32_t a0, uint32_t a1, uint32_t a2, uint32_t a3,
                                            uint32_t b0, uint32_t b1) {
    asm volatile(
        "mma.sync.aligned.m16n8k8.row.col.f32.tf32.tf32.f32 "
        "{%0,%1,%2,%3}, {%4,%5,%6,%7}, {%8,%9}, {%0,%1,%2,%3};"
        : "+f"(d0), "+f"(d1), "+f"(d2), "+f"(d3)
        : "r"(a0), "r"(a1), "r"(a2), "r"(a3), "r"(b0), "r"(b1));
}
// D += A(16x16) @ B(16x8), fp16 in, fp32 accum.
__device__ __forceinline__ void mma_f16_k16(float& d0, float& d1, float& d2, float& d3,
                                            uint32_t a0, uint32_t a1, uint32_t a2, uint32_t a3,
                                            uint32_t b0, uint32_t b1) {
    asm volatile(
        "mma.sync.aligned.m16n8k16.row.col.f32.f16.f16.f32 "
        "{%0,%1,%2,%3}, {%4,%5,%6,%7}, {%8,%9}, {%0,%1,%2,%3};"
        : "+f"(d0), "+f"(d1), "+f"(d2), "+f"(d3)
        : "r"(a0), "r"(a1), "r"(a2), "r"(a3), "r"(b0), "r"(b1));
}

// ---------------------------------------------------------------------------
// Projection: q/k/v = xf @ W^T + b -> [bh, l, 8].
// ---------------------------------------------------------------------------
__global__ __launch_bounds__(256) void proj_kernel(
    const float* __restrict__ x,
    const float* __restrict__ Wq, const float* __restrict__ bq,
    const float* __restrict__ Wk, const float* __restrict__ bk,
    const float* __restrict__ Wv, const float* __restrict__ bv)
{
    extern __shared__ float sm[];
    float* Wt = sm;
    float* As = sm + 112 * 113;
    float* bs = As + 64 * 113;

    const int z = blockIdx.y;
    const float* W = (z == 0) ? Wq : ((z == 1) ? Wk : Wv);
    const float* b = (z == 0) ? bq : ((z == 1) ? bk : bv);
    float* dst     = (z == 0) ? g_Q : ((z == 1) ? g_K : g_V);
    const float scale = (z == 0) ? (1.4426950408889634f / 32.0f) : 1.0f;
    const float padv  = (z == 2) ? 1.0f : 0.0f;
    const bool  do_tf = (z != 2);

    const int tid  = threadIdx.x;
    const int row0 = blockIdx.x * 64;

    for (int e = tid; e < SZ * SZ; e += 256) {
        int o = e / SZ, i = e - o * SZ;
        Wt[i * 113 + o] = W[e];
    }
    for (int e = tid; e < 64 * SZ; e += 256) {
        int r = e / SZ, i = e - r * SZ;
        int row = row0 + r;
        int n = row >> 10, l = row & 1023;
        int c = i / Dd, dd = i - c * Dd;
        As[r * 113 + i] = x[(((n * Cc + c) << 10) + l) * Dd + dd];
    }
    if (tid < SZ) bs[tid] = b[tid];
    __syncthreads();

    const int rr = tid >> 4, oc = tid & 15;
    float acc[4][7];
#pragma unroll
    for (int k = 0; k < 4; ++k)
#pragma unroll
        for (int j = 0; j < 7; ++j) acc[k][j] = 0.0f;

#pragma unroll 4
    for (int i = 0; i < SZ; ++i) {
        float w[7];
#pragma unroll
        for (int j = 0; j < 7; ++j) w[j] = Wt[i * 113 + oc * 7 + j];
#pragma unroll
        for (int k = 0; k < 4; ++k) {
            float a = As[(rr * 4 + k) * 113 + i];
#pragma unroll
            for (int j = 0; j < 7; ++j) acc[k][j] = fmaf(a, w[j], acc[k][j]);
        }
    }
#pragma unroll
    for (int k = 0; k < 4; ++k) {
        int row = row0 + rr * 4 + k;
        int n = row >> 10, l = row & 1023;
        float4* p = (float4*)(dst + (((n * Hh + oc) << 10) + l) * PAD);
        float r0 = (acc[k][0] + bs[oc * 7 + 0]) * scale;
        float r1 = (acc[k][1] + bs[oc * 7 + 1]) * scale;
        float r2 = (acc[k][2] + bs[oc * 7 + 2]) * scale;
        float r3 = (acc[k][3] + bs[oc * 7 + 3]) * scale;
        float r4 = (acc[k][4] + bs[oc * 7 + 4]) * scale;
        float r5 = (acc[k][5] + bs[oc * 7 + 5]) * scale;
        float r6 = (acc[k][6] + bs[oc * 7 + 6]) * scale;
        if (do_tf) {
            r0 = tf32r(r0); r1 = tf32r(r1); r2 = tf32r(r2); r3 = tf32r(r3);
            r4 = tf32r(r4); r5 = tf32r(r5); r6 = tf32r(r6);
        }
        p[0] = make_float4(r0, r1, r2, r3);
        p[1] = make_float4(r4, r5, r6, padv);
    }
}

// ---------------------------------------------------------------------------
// Warp-MMA attention, shuffle-free. CTA = (qtile, bh): 128 q x 1024 k,
// 8 warps x 16 query rows. Per 16-key step: 2 tf32 QK MMAs -> 8 ex2 ->
// 4 f16x2 packs (QK C-frag == fp16 A-frag layout, no shuffles) ->
// 1 m16n8k16 fp16 AV MMA. V pre-packed half2 (key pairs), dim7 = 1 -> denom.
// SMEM: KT fp32 [8][1032] (33024 B) + Vp half2 [512][8] (16384 B) = 49408 B.
// ---------------------------------------------------------------------------
__global__ __launch_bounds__(256) void attn_kernel(float* __restrict__ out)
{
    extern __shared__ char smem[];
    float*   KT = (float*)smem;               // [8][1032]
    __half2* Vp = (__half2*)(smem + 33024);   // [512][8]: (V[2k],V[2k+1])[dim]

    const int tid = threadIdx.x;
    const int wid = tid >> 5, lid = tid & 31;
    const int g = lid >> 2, t = lid & 3;
    const int qt = blockIdx.x;
    const int bh = blockIdx.y;

    // Stage K^T (fp32 tf32-rounded).
    const float* gK = g_K + bh * Ll * PAD;
    for (int e = tid; e < 8192; e += 256) {
        int key = e >> 3, dim = e & 7;
        KT[dim * 1032 + key] = gK[e];
    }
    // Stage V packed: Vp[k2][dim] = half2(V[2k2][dim], V[2k2+1][dim]).
    {
        const float4* gV4 = (const float4*)(g_V + bh * Ll * PAD);
        for (int k2 = tid; k2 < 512; k2 += 256) {
            float4 e0a = gV4[k2 * 4 + 0], e0b = gV4[k2 * 4 + 1];
            float4 e1a = gV4[k2 * 4 + 2], e1b = gV4[k2 * 4 + 3];
            uint32_t* d = (uint32_t*)(Vp + k2 * 8);
            d[0] = f16x2(e0a.x, e1a.x);
            d[1] = f16x2(e0a.y, e1a.y);
            d[2] = f16x2(e0a.z, e1a.z);
            d[3] = f16x2(e0a.w, e1a.w);
            d[4] = f16x2(e0b.x, e1b.x);
            d[5] = f16x2(e0b.y, e1b.y);
            d[6] = f16x2(e0b.z, e1b.z);
            d[7] = f16x2(e0b.w, e1b.w);
        }
    }

    // Q A-fragment (rows wid*16 + {g, g+8}, k-dims {t, t+4}).
    const float* qb = g_Q + (bh * Ll + qt * 128 + wid * 16) * PAD;
    const uint32_t qa0 = __float_as_uint(qb[g * 8 + t]);
    const uint32_t qa1 = __float_as_uint(qb[(g + 8) * 8 + t]);
    const uint32_t qa2 = __float_as_uint(qb[g * 8 + t + 4]);
    const uint32_t qa3 = __float_as_uint(qb[(g + 8) * 8 + t + 4]);
    __syncthreads();

    float o0 = 0.f, o1 = 0.f, o2 = 0.f, o3 = 0.f;   // out frag (cols=dims, col7=denom)

    const uint32_t* Vpu = (const uint32_t*)Vp;
    const float* KTt0 = KT + t * 1032;
    const float* KTt4 = KT + (t + 4) * 1032;

#pragma unroll 4
    for (int c = 0; c < 64; ++c) {
        const int k0 = c * 16;
        // --- QK: two 8-key tf32 MMAs (scores in log2 domain) ---
        uint32_t ka0 = __float_as_uint(KTt0[k0 + g]);
        uint32_t ka1 = __float_as_uint(KTt4[k0 + g]);
        uint32_t kb0 = __float_as_uint(KTt0[k0 + 8 + g]);
        uint32_t kb1 = __float_as_uint(KTt4[k0 + 8 + g]);
        float sa0 = 0.f, sa1 = 0.f, sa2 = 0.f, sa3 = 0.f;
        float sb0 = 0.f, sb1 = 0.f, sb2 = 0.f, sb3 = 0.f;
        mma_tf32_k8(sa0, sa1, sa2, sa3, qa0, qa1, qa2, qa3, ka0, ka1);
        mma_tf32_k8(sb0, sb1, sb2, sb3, qa0, qa1, qa2, qa3, kb0, kb1);

        // --- softmax weights; pack straight into fp16 A-frag layout ---
        uint32_t wa0 = f16x2(ex2f(sa0), ex2f(sa1));
        uint32_t wa1 = f16x2(ex2f(sa2), ex2f(sa3));
        uint32_t wa2 = f16x2(ex2f(sb0), ex2f(sb1));
        uint32_t wa3 = f16x2(ex2f(sb2), ex2f(sb3));

        // --- AV: one k16 fp16 MMA; B-frag from packed V (conflict-free) ---
        uint32_t vb0 = Vpu[(c * 8 + t) * 8 + g];
        uint32_t vb1 = Vpu[(c * 8 + t + 4) * 8 + g];
        mma_f16_k16(o0, o1, o2, o3, wa0, wa1, wa2, wa3, vb0, vb1);
    }

    // Denominator = col 7, held by lane (g,3) in o1 (row g) / o3 (row g+8).
    float sum0 = __shfl_sync(0xffffffffu, o1, (lid & ~3) | 3);
    float sum1 = __shfl_sync(0xffffffffu, o3, (lid & ~3) | 3);
    float i0 = 1.0f / sum0, i1 = 1.0f / sum1;

    const int row = bh * Ll + qt * 128 + wid * 16 + g;
    float* p0 = out + row * Dd;
    float* p1 = out + (row + 8) * Dd;
    p0[2 * t] = o0 * i0;
    p1[2 * t] = o2 * i1;
    if (t < 3) {
        p0[2 * t + 1] = o1 * i0;
        p1[2 * t + 1] = o3 * i1;
    }
}

extern "C" void kernel_launch(void* const* d_in, const int* in_sizes, int n_in,
                              void* d_out, int out_size)
{
    const float* x  = (const float*)d_in[0];
    const float* Wq = (const float*)d_in[1];
    const float* bq = (const float*)d_in[2];
    const float* Wk = (const float*)d_in[3];
    const float* bk = (const float*)d_in[4];
    const float* Wv = (const float*)d_in[5];
    const float* bv = (const float*)d_in[6];

    cudaFuncSetAttribute(proj_kernel, cudaFuncAttributeMaxDynamicSharedMemorySize, 98304);
    cudaFuncSetAttribute(attn_kernel, cudaFuncAttributeMaxDynamicSharedMemorySize, 49408);

    proj_kernel<<<dim3(128, 3, 1), 256, 98304>>>(x, Wq, bq, Wk, bk, Wv, bv);
    attn_kernel<<<dim3(8, 128, 1), 256, 49408>>>((float*)d_out);
}